// round 1
// baseline (speedup 1.0000x reference)
#include <cuda_runtime.h>
#include <math.h>
#include <float.h>

#define BB 2
#define TT 1024
#define DD 2048
#define HH 16
#define DH 128
#define NM 2048
#define WND 256
#define KTOP 8
#define BT (BB*TT)      /* 2048 */
#define BNM (BB*NM)     /* 4096 */

// ---------------- scratch (static device arrays; no allocation) ----------------
__device__ float g_q[BT*DD];
__device__ float g_k[BT*DD];
__device__ float g_v[BT*DD];
__device__ float g_kmem[BNM*DD];
__device__ float g_vmem[BNM*DD];
__device__ float g_olocal[BT*DD];
__device__ float g_cat[(size_t)BT*2*DD];
__device__ float g_sims[(size_t)BB*HH*TT*NM];

// ---------------- generic NT GEMM: C = alpha * A[M,K] * B[N,K]^T (+bias) -------
// 128x128 tile, BK=8, 256 threads, 8x8 per thread. Batched via blockIdx.z with
// two-level offset (z0 = z/zdiv, z1 = z%zdiv).
__global__ __launch_bounds__(256) void gemm_nt(
    const float* __restrict__ A, const float* __restrict__ Bm,
    float* __restrict__ C, const float* __restrict__ bias,
    int K, int lda, int ldb, int ldc,
    long long sA0, long long sA1, long long sB0, long long sB1,
    long long sC0, long long sC1, int zdiv, float alpha)
{
    int z = blockIdx.z;
    int z0 = z / zdiv, z1 = z - z0 * zdiv;
    A  += z0 * sA0 + z1 * sA1;
    Bm += z0 * sB0 + z1 * sB1;
    C  += z0 * sC0 + z1 * sC1;

    __shared__ float As[8][132];
    __shared__ float Bs[8][132];

    int tid = threadIdx.x;
    int tx = tid & 15, ty = tid >> 4;
    int row0 = blockIdx.y * 128;
    int col0 = blockIdx.x * 128;

    int lr = tid >> 1;           // 0..127
    int lk = (tid & 1) << 2;     // 0 or 4

    const float* Ag = A  + (long long)(row0 + lr) * lda + lk;
    const float* Bg = Bm + (long long)(col0 + lr) * ldb + lk;

    float acc[8][8];
    #pragma unroll
    for (int i = 0; i < 8; i++)
        #pragma unroll
        for (int j = 0; j < 8; j++) acc[i][j] = 0.f;

    for (int k0 = 0; k0 < K; k0 += 8) {
        float4 av = *(const float4*)(Ag + k0);
        float4 bv = *(const float4*)(Bg + k0);
        __syncthreads();
        As[lk+0][lr] = av.x; As[lk+1][lr] = av.y; As[lk+2][lr] = av.z; As[lk+3][lr] = av.w;
        Bs[lk+0][lr] = bv.x; Bs[lk+1][lr] = bv.y; Bs[lk+2][lr] = bv.z; Bs[lk+3][lr] = bv.w;
        __syncthreads();
        #pragma unroll
        for (int kk = 0; kk < 8; kk++) {
            float4 a0 = *(const float4*)&As[kk][ty*8];
            float4 a1 = *(const float4*)&As[kk][ty*8+4];
            float4 b0 = *(const float4*)&Bs[kk][tx*8];
            float4 b1 = *(const float4*)&Bs[kk][tx*8+4];
            float a[8] = {a0.x,a0.y,a0.z,a0.w,a1.x,a1.y,a1.z,a1.w};
            float b[8] = {b0.x,b0.y,b0.z,b0.w,b1.x,b1.y,b1.z,b1.w};
            #pragma unroll
            for (int i = 0; i < 8; i++)
                #pragma unroll
                for (int j = 0; j < 8; j++)
                    acc[i][j] = fmaf(a[i], b[j], acc[i][j]);
        }
    }

    #pragma unroll
    for (int i = 0; i < 8; i++) {
        long long ro = (long long)(row0 + ty*8 + i) * ldc + col0 + tx*8;
        #pragma unroll
        for (int j = 0; j < 8; j++) {
            float r = alpha * acc[i][j];
            if (bias) r += bias[col0 + tx*8 + j];
            C[ro + j] = r;
        }
    }
}

// ---------------- RoPE (in-place, q and k) ----------------
__global__ void rope_kernel(float* __restrict__ q, float* __restrict__ k,
                            const float* __restrict__ cs, const float* __restrict__ sn)
{
    int idx = blockIdx.x * blockDim.x + threadIdx.x;
    if (idx >= BT * DD / 2) return;
    int half = idx & 63;
    int h = (idx >> 6) & (HH - 1);
    int bt = idx >> 10;              // 64 * 16 = 1024 pairs per (b,t)
    int base = bt * DD + h * DH;
    float c1 = cs[bt*DH + half],      s1 = sn[bt*DH + half];
    float c2 = cs[bt*DH + half + 64], s2 = sn[bt*DH + half + 64];
    float q1 = q[base + half], q2 = q[base + half + 64];
    q[base + half]      = q1 * c1 - q2 * s1;
    q[base + half + 64] = q2 * c2 + q1 * s2;
    float k1 = k[base + half], k2 = k[base + half + 64];
    k[base + half]      = k1 * c1 - k2 * s1;
    k[base + half + 64] = k2 * c2 + k1 * s2;
}

// ---------------- banded local attention ----------------
// grid (T/8, H, B), 256 threads = 8 warps, warp w owns query t0+w.
__global__ __launch_bounds__(256) void local_attn(
    const float* __restrict__ q, const float* __restrict__ k,
    const float* __restrict__ v, float* __restrict__ o)
{
    int b = blockIdx.z, h = blockIdx.y;
    int t0 = blockIdx.x * 8;
    int w = threadIdx.x >> 5, lane = threadIdx.x & 31;

    __shared__ float qs[8][128];
    __shared__ float sc[8][WND];

    for (int x = threadIdx.x; x < 8 * 128; x += 256) {
        int qq = x >> 7, i = x & 127;
        qs[qq][i] = q[(size_t)(b*TT + t0 + qq) * DD + h*DH + i];
    }
    __syncthreads();

    int t = t0 + w;
    int jlo = t - (WND - 1); if (jlo < 0) jlo = 0;
    int L = t - jlo + 1;
    const float scale = 0.0883883476483184406f;  // 1/sqrt(128)

    const float4* q4 = (const float4*)qs[w];
    float lm = -FLT_MAX;
    for (int jj = lane; jj < L; jj += 32) {
        const float4* k4 = (const float4*)(k + (size_t)(b*TT + jlo + jj) * DD + h*DH);
        float s = 0.f;
        #pragma unroll 8
        for (int ii = 0; ii < 32; ii++) {
            float4 kv = k4[ii]; float4 qv = q4[ii];
            s = fmaf(qv.x, kv.x, s); s = fmaf(qv.y, kv.y, s);
            s = fmaf(qv.z, kv.z, s); s = fmaf(qv.w, kv.w, s);
        }
        s *= scale;
        sc[w][jj] = s;
        lm = fmaxf(lm, s);
    }
    #pragma unroll
    for (int off = 16; off; off >>= 1)
        lm = fmaxf(lm, __shfl_xor_sync(0xffffffffu, lm, off));

    float ls = 0.f;
    for (int jj = lane; jj < L; jj += 32) {
        float e = __expf(sc[w][jj] - lm);
        sc[w][jj] = e;
        ls += e;
    }
    __syncwarp();
    #pragma unroll
    for (int off = 16; off; off >>= 1)
        ls += __shfl_xor_sync(0xffffffffu, ls, off);

    float4 acc = make_float4(0.f, 0.f, 0.f, 0.f);
    const float* vb = v + (size_t)(b*TT + jlo) * DD + h*DH + lane*4;
    #pragma unroll 4
    for (int jj = 0; jj < L; jj++) {
        float p = sc[w][jj];
        float4 vv = *(const float4*)(vb + (size_t)jj * DD);
        acc.x = fmaf(p, vv.x, acc.x); acc.y = fmaf(p, vv.y, acc.y);
        acc.z = fmaf(p, vv.z, acc.z); acc.w = fmaf(p, vv.w, acc.w);
    }
    float inv = 1.f / ls;
    float4 outv = make_float4(acc.x*inv, acc.y*inv, acc.z*inv, acc.w*inv);
    *(float4*)(o + (size_t)(b*TT + t) * DD + h*DH + lane*4) = outv;
}

// ---------------- top-8 over memory sims + weighted gather ----------------
// grid (T, H, B), 256 threads.
__global__ __launch_bounds__(256) void topk_attn(
    const float* __restrict__ sims, const float* __restrict__ vmem,
    float* __restrict__ cat)
{
    int b = blockIdx.z, h = blockIdx.y, t = blockIdx.x;
    __shared__ float ss[NM];
    __shared__ float rv[8]; __shared__ int ri[8];
    __shared__ float selv[KTOP]; __shared__ int seli[KTOP];
    __shared__ float wts[KTOP];

    int tid = threadIdx.x, lane = tid & 31, wrp = tid >> 5;
    const float* srow = sims + ((size_t)(b*HH + h) * TT + t) * NM;
    for (int i = tid; i < NM; i += 256) ss[i] = srow[i];
    __syncthreads();

    for (int sel = 0; sel < KTOP; sel++) {
        float bv = -FLT_MAX; int bi = 0;
        for (int i = tid; i < NM; i += 256) {
            float x = ss[i];
            if (x > bv) { bv = x; bi = i; }
        }
        #pragma unroll
        for (int off = 16; off; off >>= 1) {
            float ov = __shfl_down_sync(0xffffffffu, bv, off);
            int   oi = __shfl_down_sync(0xffffffffu, bi, off);
            if (ov > bv) { bv = ov; bi = oi; }
        }
        if (lane == 0) { rv[wrp] = bv; ri[wrp] = bi; }
        __syncthreads();
        if (tid == 0) {
            float mv = rv[0]; int mi = ri[0];
            for (int wg = 1; wg < 8; wg++)
                if (rv[wg] > mv) { mv = rv[wg]; mi = ri[wg]; }
            selv[sel] = mv; seli[sel] = mi;
            ss[mi] = -FLT_MAX;
        }
        __syncthreads();
    }

    if (tid == 0) {
        float m = selv[0], s = 0.f;
        for (int j = 0; j < KTOP; j++) { float e = __expf(selv[j] - m); wts[j] = e; s += e; }
        float inv = 1.f / s;
        for (int j = 0; j < KTOP; j++) wts[j] *= inv;
    }
    __syncthreads();

    if (tid < DH) {
        float acc = 0.f;
        #pragma unroll
        for (int j = 0; j < KTOP; j++)
            acc = fmaf(wts[j], vmem[(size_t)(b*NM + seli[j]) * DD + h*DH + tid], acc);
        cat[(size_t)(b*TT + t) * (2*DD) + DD + h*DH + tid] = acc;
    }
}

// ---------------- launch ----------------
extern "C" void kernel_launch(void* const* d_in, const int* in_sizes, int n_in,
                              void* d_out, int out_size)
{
    const float* hs  = (const float*)d_in[0];
    const float* cs  = (const float*)d_in[1];
    const float* sn  = (const float*)d_in[2];
    const float* Wq  = (const float*)d_in[3];
    const float* Wk  = (const float*)d_in[4];
    const float* Wv  = (const float*)d_in[5];
    const float* Wo  = (const float*)d_in[6];
    const float* Wf  = (const float*)d_in[7];
    const float* bf  = (const float*)d_in[8];
    const float* mem = (const float*)d_in[9];
    float* out = (float*)d_out;

    float *q, *k, *v, *kmem, *vmem, *olocal, *cat, *sims;
    cudaGetSymbolAddress((void**)&q, g_q);
    cudaGetSymbolAddress((void**)&k, g_k);
    cudaGetSymbolAddress((void**)&v, g_v);
    cudaGetSymbolAddress((void**)&kmem, g_kmem);
    cudaGetSymbolAddress((void**)&vmem, g_vmem);
    cudaGetSymbolAddress((void**)&olocal, g_olocal);
    cudaGetSymbolAddress((void**)&cat, g_cat);
    cudaGetSymbolAddress((void**)&sims, g_sims);

    dim3 blk(256);
    const float scale = 0.0883883476483184406f;

    // Q/K/V projections: [2048,2048] = hs[2048,2048] @ W^T
    dim3 g1(DD/128, BT/128, 1);
    gemm_nt<<<g1, blk>>>(hs, Wq, q, nullptr, DD, DD, DD, DD, 0,0,0,0,0,0, 1, 1.f);
    gemm_nt<<<g1, blk>>>(hs, Wk, k, nullptr, DD, DD, DD, DD, 0,0,0,0,0,0, 1, 1.f);
    gemm_nt<<<g1, blk>>>(hs, Wv, v, nullptr, DD, DD, DD, DD, 0,0,0,0,0,0, 1, 1.f);

    // RoPE on q, k
    rope_kernel<<<(BT*DD/2 + 255)/256, 256>>>(q, k, cs, sn);

    // memory K/V projections: [4096,2048]
    dim3 g2(DD/128, BNM/128, 1);
    gemm_nt<<<g2, blk>>>(mem, Wk, kmem, nullptr, DD, DD, DD, DD, 0,0,0,0,0,0, 1, 1.f);
    gemm_nt<<<g2, blk>>>(mem, Wv, vmem, nullptr, DD, DD, DD, DD, 0,0,0,0,0,0, 1, 1.f);

    // banded local attention
    local_attn<<<dim3(TT/8, HH, BB), 256>>>(q, k, v, olocal);

    // o_local @ Wo^T -> first half of cat (ldc = 2D)
    gemm_nt<<<g1, blk>>>(olocal, Wo, cat, nullptr, DD, DD, DD, 2*DD, 0,0,0,0,0,0, 1, 1.f);

    // sims[b,h,t,n] = scale * q . k_mem  (batched over z = b*H + h)
    dim3 g3(NM/128, TT/128, BB*HH);
    gemm_nt<<<g3, blk>>>(q, kmem, sims, nullptr, DH, DD, DD, NM,
                         (long long)TT*DD, (long long)DH,
                         (long long)NM*DD, (long long)DH,
                         (long long)HH*TT*NM, (long long)TT*NM,
                         HH, scale);

    // top-8 + softmax + gather -> second half of cat
    topk_attn<<<dim3(TT, HH, BB), 256>>>(sims, vmem, cat);

    // final: out = cat[2048,4096] @ Wf^T + bf
    dim3 g4(DD/128, BT/128, 1);
    gemm_nt<<<g4, blk>>>(cat, Wf, out, bf, 2*DD, 2*DD, 2*DD, DD, 0,0,0,0,0,0, 1, 1.f);
}

// round 17
// speedup vs baseline: 1.1163x; 1.1163x over previous
#include <cuda_runtime.h>
#include <cuda_bf16.h>
#include <cstdint>
#include <math.h>
#include <float.h>

typedef unsigned int u32;
typedef __nv_bfloat16 bf16;

#define BB 2
#define TT 1024
#define DD 2048
#define HH 16
#define DH 128
#define NM 2048
#define WND 256
#define KTOP 8
#define BT (BB*TT)      /* 2048 */
#define BNM (BB*NM)     /* 4096 */

#define SP_HS  ((long long)BT*DD)
#define SP_MEM ((long long)BNM*DD)
#define SP_W   ((long long)DD*DD)
#define SP_WF  ((long long)2*DD*DD)
#define SP_CAT ((long long)BT*2*DD)

// ---------------- scratch (static; no allocation) ----------------
__device__ float g_q[BT*DD];
__device__ float g_k[BT*DD];
__device__ float g_v[BT*DD];
__device__ float g_kmem[(size_t)BNM*DD];
__device__ float g_vmem[(size_t)BNM*DD];
__device__ float g_sims[(size_t)BB*HH*TT*NM];

__device__ bf16 g_hs3[3ull*BT*DD];
__device__ bf16 g_mem3[3ull*BNM*DD];
__device__ bf16 g_wk3[3ull*DD*DD];
__device__ bf16 g_wv3[3ull*DD*DD];
__device__ bf16 g_wo3[3ull*DD*DD];
__device__ bf16 g_wf3[3ull*2*DD*DD];
__device__ bf16 g_ol3[3ull*BT*DD];
__device__ bf16 g_cat3[3ull*BT*2*DD];

// ---------------- helpers ----------------
__device__ __forceinline__ u32 smem_addr(const void* p) {
    u32 a;
    asm("{ .reg .u64 t; cvta.to.shared.u64 t, %1; cvt.u32.u64 %0, t; }" : "=r"(a) : "l"(p));
    return a;
}
__device__ __forceinline__ void mma_bf16(float* c, const u32* a, const u32* b) {
    asm volatile(
        "mma.sync.aligned.m16n8k16.row.col.f32.bf16.bf16.f32 "
        "{%0,%1,%2,%3}, {%4,%5,%6,%7}, {%8,%9}, {%0,%1,%2,%3};"
        : "+f"(c[0]), "+f"(c[1]), "+f"(c[2]), "+f"(c[3])
        : "r"(a[0]), "r"(a[1]), "r"(a[2]), "r"(a[3]), "r"(b[0]), "r"(b[1]));
}
__device__ __forceinline__ void cp16(u32 s, const void* g) {
    asm volatile("cp.async.ca.shared.global [%0], [%1], 16;" :: "r"(s), "l"(g));
}
__device__ __forceinline__ void split3(float x, bf16& h1, bf16& h2, bf16& h3) {
    h1 = __float2bfloat16(x);
    float r1 = x - __bfloat162float(h1);
    h2 = __float2bfloat16(r1);
    h3 = __float2bfloat16(r1 - __bfloat162float(h2));
}

// ================= FFMA fp32 GEMM (exact; R1-proven) =================
// C = alpha * A[M,K] * B[N,K]^T (+bias). 128x128 tile, BK=8, 8x8/thread.
__global__ __launch_bounds__(256) void gemm_nt(
    const float* __restrict__ A, const float* __restrict__ Bm,
    float* __restrict__ C, const float* __restrict__ bias,
    int K, int lda, int ldb, int ldc,
    long long sA0, long long sA1, long long sB0, long long sB1,
    long long sC0, long long sC1, int zdiv, float alpha)
{
    int z = blockIdx.z;
    int z0 = z / zdiv, z1 = z - z0 * zdiv;
    A  += z0 * sA0 + z1 * sA1;
    Bm += z0 * sB0 + z1 * sB1;
    C  += z0 * sC0 + z1 * sC1;

    __shared__ float As[8][132];
    __shared__ float Bs[8][132];

    int tid = threadIdx.x;
    int tx = tid & 15, ty = tid >> 4;
    int row0 = blockIdx.y * 128;
    int col0 = blockIdx.x * 128;

    int lr = tid >> 1;
    int lk = (tid & 1) << 2;

    const float* Ag = A  + (long long)(row0 + lr) * lda + lk;
    const float* Bg = Bm + (long long)(col0 + lr) * ldb + lk;

    float acc[8][8];
    #pragma unroll
    for (int i = 0; i < 8; i++)
        #pragma unroll
        for (int j = 0; j < 8; j++) acc[i][j] = 0.f;

    for (int k0 = 0; k0 < K; k0 += 8) {
        float4 av = *(const float4*)(Ag + k0);
        float4 bv = *(const float4*)(Bg + k0);
        __syncthreads();
        As[lk+0][lr] = av.x; As[lk+1][lr] = av.y; As[lk+2][lr] = av.z; As[lk+3][lr] = av.w;
        Bs[lk+0][lr] = bv.x; Bs[lk+1][lr] = bv.y; Bs[lk+2][lr] = bv.z; Bs[lk+3][lr] = bv.w;
        __syncthreads();
        #pragma unroll
        for (int kk = 0; kk < 8; kk++) {
            float4 a0 = *(const float4*)&As[kk][ty*8];
            float4 a1 = *(const float4*)&As[kk][ty*8+4];
            float4 b0 = *(const float4*)&Bs[kk][tx*8];
            float4 b1 = *(const float4*)&Bs[kk][tx*8+4];
            float a[8] = {a0.x,a0.y,a0.z,a0.w,a1.x,a1.y,a1.z,a1.w};
            float b[8] = {b0.x,b0.y,b0.z,b0.w,b1.x,b1.y,b1.z,b1.w};
            #pragma unroll
            for (int i = 0; i < 8; i++)
                #pragma unroll
                for (int j = 0; j < 8; j++)
                    acc[i][j] = fmaf(a[i], b[j], acc[i][j]);
        }
    }

    #pragma unroll
    for (int i = 0; i < 8; i++) {
        long long ro = (long long)(row0 + ty*8 + i) * ldc + col0 + tx*8;
        #pragma unroll
        for (int j = 0; j < 8; j++) {
            float r = alpha * acc[i][j];
            if (bias) r += bias[col0 + tx*8 + j];
            C[ro + j] = r;
        }
    }
}

// ========== 6-pass 3-way-bf16-split tensor-core GEMM ==========
#define HPITCH 40
#define ROWU   (HPITCH/2)
#define PLANEU (128*ROWU)
#define MATU   (3*PLANEU)
#define STAGEU (2*MATU)
#define SMEM_BYTES (2*STAGEU*4)

__global__ __launch_bounds__(256) void gemm_tc(
    const bf16* __restrict__ A, long long spA,
    const bf16* __restrict__ B, long long spB,
    float* __restrict__ C, bf16* __restrict__ C3, long long spC3,
    const float* __restrict__ bias,
    int K, int lda, int ldb, int ldc,
    long long sA0, long long sA1, long long sB0, long long sB1,
    long long sC0, long long sC1, int zdiv, float alpha)
{
    extern __shared__ u32 sm[];

    int z = blockIdx.z;
    int z0 = z / zdiv, z1 = z - z0 * zdiv;
    A += z0 * sA0 + z1 * sA1;
    B += z0 * sB0 + z1 * sB1;
    long long cofs = z0 * sC0 + z1 * sC1;
    if (C)  C  += cofs;
    if (C3) C3 += cofs;

    const int tid = threadIdx.x;
    const int wid = tid >> 5, lane = tid & 31;
    const int gr = lane >> 2, gc = lane & 3;
    const int warp_m = wid >> 2;
    const int warp_n = wid & 3;
    const int row0 = blockIdx.y * 128;
    const int col0 = blockIdx.x * 128;

    const u32 smbase = smem_addr(sm);

    float acc[4][4][4];
    #pragma unroll
    for (int mt = 0; mt < 4; mt++)
        #pragma unroll
        for (int nt = 0; nt < 4; nt++)
            #pragma unroll
            for (int r = 0; r < 4; r++) acc[mt][nt][r] = 0.f;

    const int nk = K >> 5;

    {
        #pragma unroll
        for (int t = 0; t < 6; t++) {
            int i = tid + t*256;
            int pl = i >> 9, row = (i >> 2) & 127, seg = i & 3;
            u32 off = (u32)(pl*PLANEU + row*ROWU + seg*4);
            cp16(smbase + off*4,
                 A + (size_t)pl*spA + (size_t)(row0+row)*lda + seg*8);
            cp16(smbase + (off + MATU)*4,
                 B + (size_t)pl*spB + (size_t)(col0+row)*ldb + seg*8);
        }
        asm volatile("cp.async.commit_group;");
    }

    for (int c = 0; c < nk; c++) {
        const int st = c & 1;
        asm volatile("cp.async.wait_group 0;" ::: "memory");
        __syncthreads();
        if (c + 1 < nk) {
            const int sn = (c + 1) & 1;
            const int kc = (c + 1) << 5;
            #pragma unroll
            for (int t = 0; t < 6; t++) {
                int i = tid + t*256;
                int pl = i >> 9, row = (i >> 2) & 127, seg = i & 3;
                u32 off = (u32)(sn*STAGEU + pl*PLANEU + row*ROWU + seg*4);
                cp16(smbase + off*4,
                     A + (size_t)pl*spA + (size_t)(row0+row)*lda + kc + seg*8);
                cp16(smbase + (off + MATU)*4,
                     B + (size_t)pl*spB + (size_t)(col0+row)*ldb + kc + seg*8);
            }
            asm volatile("cp.async.commit_group;");
        }

        const u32* Au = sm + st*STAGEU;
        const u32* Bu = Au + MATU;

        #pragma unroll
        for (int ks = 0; ks < 2; ks++) {
            u32 b[3][4][2];
            #pragma unroll
            for (int p = 0; p < 3; p++)
                #pragma unroll
                for (int nt = 0; nt < 4; nt++) {
                    int o = p*PLANEU + (warp_n*32 + nt*8)*ROWU + ks*8 + gr*ROWU + gc;
                    b[p][nt][0] = Bu[o];
                    b[p][nt][1] = Bu[o + 4];
                }
            #pragma unroll
            for (int mt = 0; mt < 4; mt++) {
                u32 a[3][4];
                #pragma unroll
                for (int p = 0; p < 3; p++) {
                    int o = p*PLANEU + (warp_m*64 + mt*16)*ROWU + ks*8 + gr*ROWU + gc;
                    a[p][0] = Au[o];
                    a[p][1] = Au[o + 8*ROWU];
                    a[p][2] = Au[o + 4];
                    a[p][3] = Au[o + 8*ROWU + 4];
                }
                #pragma unroll
                for (int nt = 0; nt < 4; nt++) {
                    float* cc = acc[mt][nt];
                    mma_bf16(cc, a[0], b[0][nt]);
                    mma_bf16(cc, a[0], b[1][nt]);
                    mma_bf16(cc, a[1], b[0][nt]);
                    mma_bf16(cc, a[1], b[1][nt]);
                    mma_bf16(cc, a[0], b[2][nt]);
                    mma_bf16(cc, a[2], b[0][nt]);
                }
            }
        }
        __syncthreads();
    }

    #pragma unroll
    for (int mt = 0; mt < 4; mt++) {
        #pragma unroll
        for (int nt = 0; nt < 4; nt++) {
            int r  = row0 + warp_m*64 + mt*16 + gr;
            int cc = col0 + warp_n*32 + nt*8 + gc*2;
            float b0 = bias ? bias[cc]   : 0.f;
            float b1 = bias ? bias[cc+1] : 0.f;
            float v00 = acc[mt][nt][0]*alpha + b0;
            float v01 = acc[mt][nt][1]*alpha + b1;
            float v10 = acc[mt][nt][2]*alpha + b0;
            float v11 = acc[mt][nt][3]*alpha + b1;
            if (C) {
                *(float2*)(C + (size_t)r*ldc + cc)     = make_float2(v00, v01);
                *(float2*)(C + (size_t)(r+8)*ldc + cc) = make_float2(v10, v11);
            }
            if (C3) {
                long long o0 = (long long)r*ldc + cc;
                long long o1 = (long long)(r+8)*ldc + cc;
                bf16 h1, h2, h3;
                split3(v00, h1, h2, h3);
                C3[o0] = h1; C3[o0 + spC3] = h2; C3[o0 + 2*spC3] = h3;
                split3(v01, h1, h2, h3);
                C3[o0+1] = h1; C3[o0+1 + spC3] = h2; C3[o0+1 + 2*spC3] = h3;
                split3(v10, h1, h2, h3);
                C3[o1] = h1; C3[o1 + spC3] = h2; C3[o1 + 2*spC3] = h3;
                split3(v11, h1, h2, h3);
                C3[o1+1] = h1; C3[o1+1 + spC3] = h2; C3[o1+1 + 2*spC3] = h3;
            }
        }
    }
}

// ---------------- fp32 -> 3-way bf16 split ----------------
__global__ void convert3(const float* __restrict__ x, bf16* __restrict__ o, long long n)
{
    long long i = (long long)blockIdx.x * blockDim.x + threadIdx.x;
    if (i >= n) return;
    bf16 h1, h2, h3;
    split3(x[i], h1, h2, h3);
    o[i] = h1; o[n + i] = h2; o[2*n + i] = h3;
}

// ---------------- RoPE (in-place, q and k) ----------------
__global__ void rope_kernel(float* __restrict__ q, float* __restrict__ k,
                            const float* __restrict__ cs, const float* __restrict__ sn)
{
    int idx = blockIdx.x * blockDim.x + threadIdx.x;
    if (idx >= BT * DD / 2) return;
    int half = idx & 63;
    int h = (idx >> 6) & (HH - 1);
    int bt = idx >> 10;
    int base = bt * DD + h * DH;
    float c1 = cs[bt*DH + half],      s1 = sn[bt*DH + half];
    float c2 = cs[bt*DH + half + 64], s2 = sn[bt*DH + half + 64];
    float q1 = q[base + half], q2 = q[base + half + 64];
    q[base + half]      = q1 * c1 - q2 * s1;
    q[base + half + 64] = q2 * c2 + q1 * s2;
    float k1 = k[base + half], k2 = k[base + half + 64];
    k[base + half]      = k1 * c1 - k2 * s1;
    k[base + half + 64] = k2 * c2 + k1 * s2;
}

// ---------------- banded local attention -> o_local 3-split ----------------
__global__ __launch_bounds__(256) void local_attn(
    const float* __restrict__ q, const float* __restrict__ k,
    const float* __restrict__ v, bf16* __restrict__ o3)
{
    int b = blockIdx.z, h = blockIdx.y;
    int t0 = blockIdx.x * 8;
    int w = threadIdx.x >> 5, lane = threadIdx.x & 31;

    __shared__ float qs[8][128];
    __shared__ float sc[8][WND];

    for (int x = threadIdx.x; x < 8 * 128; x += 256) {
        int qq = x >> 7, i = x & 127;
        qs[qq][i] = q[(size_t)(b*TT + t0 + qq) * DD + h*DH + i];
    }
    __syncthreads();

    int t = t0 + w;
    int jlo = t - (WND - 1); if (jlo < 0) jlo = 0;
    int L = t - jlo + 1;
    const float scale = 0.0883883476483184406f;

    const float4* q4 = (const float4*)qs[w];
    float lm = -FLT_MAX;
    for (int jj = lane; jj < L; jj += 32) {
        const float4* k4 = (const float4*)(k + (size_t)(b*TT + jlo + jj) * DD + h*DH);
        float s = 0.f;
        #pragma unroll 8
        for (int ii = 0; ii < 32; ii++) {
            float4 kv = k4[ii]; float4 qv = q4[ii];
            s = fmaf(qv.x, kv.x, s); s = fmaf(qv.y, kv.y, s);
            s = fmaf(qv.z, kv.z, s); s = fmaf(qv.w, kv.w, s);
        }
        s *= scale;
        sc[w][jj] = s;
        lm = fmaxf(lm, s);
    }
    #pragma unroll
    for (int off = 16; off; off >>= 1)
        lm = fmaxf(lm, __shfl_xor_sync(0xffffffffu, lm, off));

    float ls = 0.f;
    for (int jj = lane; jj < L; jj += 32) {
        float e = __expf(sc[w][jj] - lm);
        sc[w][jj] = e;
        ls += e;
    }
    __syncwarp();
    #pragma unroll
    for (int off = 16; off; off >>= 1)
        ls += __shfl_xor_sync(0xffffffffu, ls, off);

    float4 acc = make_float4(0.f, 0.f, 0.f, 0.f);
    const float* vb = v + (size_t)(b*TT + jlo) * DD + h*DH + lane*4;
    #pragma unroll 4
    for (int jj = 0; jj < L; jj++) {
        float p = sc[w][jj];
        float4 vv = *(const float4*)(vb + (size_t)jj * DD);
        acc.x = fmaf(p, vv.x, acc.x); acc.y = fmaf(p, vv.y, acc.y);
        acc.z = fmaf(p, vv.z, acc.z); acc.w = fmaf(p, vv.w, acc.w);
    }
    float inv = 1.f / ls;
    float vals[4] = {acc.x*inv, acc.y*inv, acc.z*inv, acc.w*inv};
    long long base = (long long)(b*TT + t) * DD + h*DH + lane*4;
    #pragma unroll
    for (int c = 0; c < 4; c++) {
        bf16 h1, h2, h3;
        split3(vals[c], h1, h2, h3);
        o3[base + c]           = h1;
        o3[base + c + SP_HS]   = h2;
        o3[base + c + 2*SP_HS] = h3;
    }
}

// ---------------- top-8 + weighted gather -> cat 3-split (mem half) -------
__global__ __launch_bounds__(256) void topk_attn(
    const float* __restrict__ sims, const float* __restrict__ vmem,
    bf16* __restrict__ cat3)
{
    int b = blockIdx.z, h = blockIdx.y, t = blockIdx.x;
    __shared__ float ss[NM];
    __shared__ float rv[8]; __shared__ int ri[8];
    __shared__ float selv[KTOP]; __shared__ int seli[KTOP];
    __shared__ float wts[KTOP];

    int tid = threadIdx.x, lane = tid & 31, wrp = tid >> 5;
    const float* srow = sims + ((size_t)(b*HH + h) * TT + t) * NM;
    for (int i = tid; i < NM; i += 256) ss[i] = srow[i];
    __syncthreads();

    for (int sel = 0; sel < KTOP; sel++) {
        float bv = -FLT_MAX; int bi = 0;
        for (int i = tid; i < NM; i += 256) {
            float x = ss[i];
            if (x > bv) { bv = x; bi = i; }
        }
        #pragma unroll
        for (int off = 16; off; off >>= 1) {
            float ov = __shfl_down_sync(0xffffffffu, bv, off);
            int   oi = __shfl_down_sync(0xffffffffu, bi, off);
            if (ov > bv) { bv = ov; bi = oi; }
        }
        if (lane == 0) { rv[wrp] = bv; ri[wrp] = bi; }
        __syncthreads();
        if (tid == 0) {
            float mv = rv[0]; int mi = ri[0];
            for (int wg = 1; wg < 8; wg++)
                if (rv[wg] > mv) { mv = rv[wg]; mi = ri[wg]; }
            selv[sel] = mv; seli[sel] = mi;
            ss[mi] = -FLT_MAX;
        }
        __syncthreads();
    }

    if (tid == 0) {
        float m = selv[0], s = 0.f;
        for (int j = 0; j < KTOP; j++) { float e = __expf(selv[j] - m); wts[j] = e; s += e; }
        float inv = 1.f / s;
        for (int j = 0; j < KTOP; j++) wts[j] *= inv;
    }
    __syncthreads();

    if (tid < DH) {
        float acc = 0.f;
        #pragma unroll
        for (int j = 0; j < KTOP; j++)
            acc = fmaf(wts[j], vmem[(size_t)(b*NM + seli[j]) * DD + h*DH + tid], acc);
        long long idx = (long long)(b*TT + t) * (2*DD) + DD + h*DH + tid;
        bf16 h1, h2, h3;
        split3(acc, h1, h2, h3);
        cat3[idx]            = h1;
        cat3[idx + SP_CAT]   = h2;
        cat3[idx + 2*SP_CAT] = h3;
    }
}

// ---------------- launch ----------------
extern "C" void kernel_launch(void* const* d_in, const int* in_sizes, int n_in,
                              void* d_out, int out_size)
{
    const float* hs  = (const float*)d_in[0];
    const float* cs  = (const float*)d_in[1];
    const float* sn  = (const float*)d_in[2];
    const float* Wq  = (const float*)d_in[3];
    const float* Wk  = (const float*)d_in[4];
    const float* Wv  = (const float*)d_in[5];
    const float* Wo  = (const float*)d_in[6];
    const float* Wf  = (const float*)d_in[7];
    const float* bfv = (const float*)d_in[8];
    const float* mem = (const float*)d_in[9];
    float* out = (float*)d_out;

    float* q;    cudaGetSymbolAddress((void**)&q,    g_q);
    float* k;    cudaGetSymbolAddress((void**)&k,    g_k);
    float* v;    cudaGetSymbolAddress((void**)&v,    g_v);
    float* kmem; cudaGetSymbolAddress((void**)&kmem, g_kmem);
    float* vmem; cudaGetSymbolAddress((void**)&vmem, g_vmem);
    float* sims; cudaGetSymbolAddress((void**)&sims, g_sims);
    bf16* hs3;   cudaGetSymbolAddress((void**)&hs3,  g_hs3);
    bf16* mem3;  cudaGetSymbolAddress((void**)&mem3, g_mem3);
    bf16* wk3;   cudaGetSymbolAddress((void**)&wk3,  g_wk3);
    bf16* wv3;   cudaGetSymbolAddress((void**)&wv3,  g_wv3);
    bf16* wo3;   cudaGetSymbolAddress((void**)&wo3,  g_wo3);
    bf16* wf3;   cudaGetSymbolAddress((void**)&wf3,  g_wf3);
    bf16* ol3;   cudaGetSymbolAddress((void**)&ol3,  g_ol3);
    bf16* cat3;  cudaGetSymbolAddress((void**)&cat3, g_cat3);

    cudaFuncSetAttribute(gemm_tc, cudaFuncAttributeMaxDynamicSharedMemorySize, SMEM_BYTES);
    const float scale = 0.0883883476483184406f;

    // split conversions (only tensor-path operands)
    convert3<<<(int)((SP_HS  + 255)/256), 256>>>(hs,  hs3,  SP_HS);
    convert3<<<(int)((SP_MEM + 255)/256), 256>>>(mem, mem3, SP_MEM);
    convert3<<<(int)((SP_W   + 255)/256), 256>>>(Wk,  wk3,  SP_W);
    convert3<<<(int)((SP_W   + 255)/256), 256>>>(Wv,  wv3,  SP_W);
    convert3<<<(int)((SP_W   + 255)/256), 256>>>(Wo,  wo3,  SP_W);
    convert3<<<(int)((SP_WF  + 255)/256), 256>>>(Wf,  wf3,  SP_WF);

    dim3 blk(256);
    dim3 g1(DD/128, BT/128, 1);
    dim3 g2(DD/128, BNM/128, 1);

    // q projection: EXACT FFMA (selection-critical)
    gemm_nt<<<g1, blk>>>(hs, Wq, q, nullptr, DD, DD, DD, DD, 0,0,0,0,0,0, 1, 1.f);
    // k, v projections: tensor
    gemm_tc<<<g1, blk, SMEM_BYTES>>>(hs3, SP_HS, wk3, SP_W, k, nullptr, 0, nullptr,
                                     DD, DD, DD, DD, 0,0,0,0,0,0, 1, 1.f);
    gemm_tc<<<g1, blk, SMEM_BYTES>>>(hs3, SP_HS, wv3, SP_W, v, nullptr, 0, nullptr,
                                     DD, DD, DD, DD, 0,0,0,0,0,0, 1, 1.f);

    rope_kernel<<<(BT*DD/2 + 255)/256, 256>>>(q, k, cs, sn);

    // kmem: EXACT FFMA (selection-critical);  vmem: tensor
    gemm_nt<<<g2, blk>>>(mem, Wk, kmem, nullptr, DD, DD, DD, DD, 0,0,0,0,0,0, 1, 1.f);
    gemm_tc<<<g2, blk, SMEM_BYTES>>>(mem3, SP_MEM, wv3, SP_W, vmem, nullptr, 0, nullptr,
                                     DD, DD, DD, DD, 0,0,0,0,0,0, 1, 1.f);

    local_attn<<<dim3(TT/8, HH, BB), 256>>>(q, k, v, ol3);

    // o_local @ Wo^T -> cat[:, 0:D] (tensor, 3-split out, ldc = 2D)
    gemm_tc<<<g1, blk, SMEM_BYTES>>>(ol3, SP_HS, wo3, SP_W, nullptr, cat3, SP_CAT, nullptr,
                                     DD, DD, DD, 2*DD, 0,0,0,0,0,0, 1, 1.f);

    // sims: EXACT FFMA (selection-critical), batched over z = b*H + h
    dim3 g3(NM/128, TT/128, BB*HH);
    gemm_nt<<<g3, blk>>>(q, kmem, sims, nullptr, DH, DD, DD, NM,
                         (long long)TT*DD, (long long)DH,
                         (long long)NM*DD, (long long)DH,
                         (long long)HH*TT*NM, (long long)TT*NM,
                         HH, scale);

    topk_attn<<<dim3(TT, HH, BB), 256>>>(sims, vmem, cat3);

    // final: out = cat @ Wf^T + bf (tensor), K=4096
    dim3 g4(DD/128, BT/128, 1);
    gemm_tc<<<g4, blk, SMEM_BYTES>>>(cat3, SP_CAT, wf3, SP_WF, out, nullptr, 0, bfv,
                                     2*DD, 2*DD, 2*DD, DD, 0,0,0,0,0,0, 1, 1.f);
}